// round 14
// baseline (speedup 1.0000x reference)
#include <cuda_runtime.h>
#include <cuda_bf16.h>
#include <cstdint>

#define B_   64
#define T_   512
#define I_   512
#define H_   512
#define G4   2048
#define NCG  128
#define BG4  (B_ * G4)
#define SEG  64                                          // timesteps per K2 launch

// ------------------------- device scratch ----------------------------------
__device__ uint4    g_WxFrag[32 * 256 * 32];            // [kb][ncf][lane] bf16 frags (Wx)
__device__ uint4    g_WhFrag[64 * 4096];                // [jc][(kb*4+nf)*32+lane] (Wh)
__device__ float    g_bias[G4];
__device__ float    g_xproj[(size_t)T_ * BG4];          // [t][b][n] fp32
__device__ uint2    g_hP[2][B_ * 256];                  // [buf][b][k2] {hi-pair, lo-pair}
__device__ float    g_cs[B_ * H_];                      // cell state between segments
__device__ int      g_count2[2];                        // per-batch-group barrier counters

// ------------------------- helpers -----------------------------------------
__device__ __forceinline__ void bsplit(float v, uint16_t& hi, uint16_t& lo) {
    __nv_bfloat16 h = __float2bfloat16_rn(v);
    float r = v - __bfloat162float(h);
    __nv_bfloat16 l = __float2bfloat16_rn(r);
    hi = __bfloat16_as_ushort(h);
    lo = __bfloat16_as_ushort(l);
}
__device__ __forceinline__ uint32_t bpack(uint16_t e0, uint16_t e1) {
    return (uint32_t)e0 | ((uint32_t)e1 << 16);
}

__device__ __forceinline__ float sigm(float x) { return 1.0f / (1.0f + __expf(-x)); }
__device__ __forceinline__ float tanh_acc(float x) {
    return 1.0f - 2.0f / (__expf(2.0f * x) + 1.0f);
}

__device__ __forceinline__ int ld_acq(const int* p) {
    int v;
    asm volatile("ld.acquire.gpu.global.b32 %0, [%1];" : "=r"(v) : "l"(p) : "memory");
    return v;
}
__device__ __forceinline__ void red_rel(int* p) {
    asm volatile("red.release.gpu.global.add.s32 [%0], %1;" :: "l"(p), "r"(1) : "memory");
}

__device__ __forceinline__ void mma_bf16(float (&d)[4], const uint32_t (&a)[4],
                                         uint32_t b0, uint32_t b1) {
    asm volatile(
        "mma.sync.aligned.m16n8k16.row.col.f32.bf16.bf16.f32 "
        "{%0,%1,%2,%3}, {%4,%5,%6,%7}, {%8,%9}, {%0,%1,%2,%3};"
        : "+f"(d[0]), "+f"(d[1]), "+f"(d[2]), "+f"(d[3])
        : "r"(a[0]), "r"(a[1]), "r"(a[2]), "r"(a[3]), "r"(b0), "r"(b1));
}

__device__ __forceinline__ const float* wsel(int gate, const float* Wf, const float* Wi,
                                             const float* Wo, const float* Wc) {
    return gate == 0 ? Wf : gate == 1 ? Wi : gate == 2 ? Wo : Wc;
}

// ------------------------- K0: pack (frozen contracts) ----------------------
__global__ void pack_kernel(const float* __restrict__ Wf, const float* __restrict__ Wi,
                            const float* __restrict__ Wo, const float* __restrict__ Wc,
                            const float* __restrict__ bf, const float* __restrict__ bi,
                            const float* __restrict__ bo, const float* __restrict__ bc) {
    int idx = blockIdx.x * blockDim.x + threadIdx.x;
    if (idx < 32 * 256 * 32) {
        int lane = idx & 31, ncf = (idx >> 5) & 255, kb = idx >> 13;
        int g = lane >> 2, tg = lane & 3;
        int k0 = kb * 16 + 2 * tg;
        int col = ncf * 8 + g;
        int gate = col >> 9, j = col & 511;
        const float* W = wsel(gate, Wf, Wi, Wo, Wc);
        float v00 = W[(size_t)k0 * H_ + j];
        float v01 = W[(size_t)(k0 + 1) * H_ + j];
        float v10 = W[(size_t)(k0 + 8) * H_ + j];
        float v11 = W[(size_t)(k0 + 9) * H_ + j];
        uint16_t h00, l00, h01, l01, h10, l10, h11, l11;
        bsplit(v00, h00, l00); bsplit(v01, h01, l01);
        bsplit(v10, h10, l10); bsplit(v11, h11, l11);
        uint4 frag;
        frag.x = bpack(h00, h01);
        frag.y = bpack(h10, h11);
        frag.z = bpack(l00, l01);
        frag.w = bpack(l10, l11);
        g_WxFrag[idx] = frag;
    }
    if (idx < 64 * 4096) {
        int lane = idx & 31, nf = (idx >> 5) & 3, kb = (idx >> 7) & 31, jc = idx >> 12;
        int g = lane >> 2, tg = lane & 3;
        int k0 = kb * 16 + 2 * tg;
        const float* W = wsel(nf, Wf, Wi, Wo, Wc);
        const size_t base = (size_t)(I_ + k0) * H_ + jc * 8 + g;
        float v00 = W[base];
        float v01 = W[base + H_];
        float v10 = W[base + 8 * H_];
        float v11 = W[base + 9 * H_];
        uint16_t h00, l00, h01, l01, h10, l10, h11, l11;
        bsplit(v00, h00, l00); bsplit(v01, h01, l01);
        bsplit(v10, h10, l10); bsplit(v11, h11, l11);
        uint4 frag;
        frag.x = bpack(h00, h01);
        frag.y = bpack(h10, h11);
        frag.z = bpack(l00, l01);
        frag.w = bpack(l10, l11);
        g_WhFrag[(size_t)jc * 4096 + (kb * 4 + nf) * 32 + lane] = frag;
    }
    if (idx < G4) {
        int gate = idx >> 9, j = idx & 511;
        const float* b = gate == 0 ? bf : gate == 1 ? bi : gate == 2 ? bo : bc;
        g_bias[idx] = b[j];
    }
    if (idx < B_ * 256) g_hP[0][idx] = make_uint2(0u, 0u);   // h_0 = 0
    if (idx < B_ * H_) g_cs[idx] = 0.0f;
    if (idx < 2) g_count2[idx] = 0;
}

// ------------------------- K1: xproj = X @ Wx + bias (3xBF16, frozen) ------
#define K1_SMEM (4 * 4 * 1280 + 2 * 512 * 16)
__global__ void __launch_bounds__(128) xproj_kernel(const float* __restrict__ x) {
    extern __shared__ char sm1raw[];
    uint32_t* sAhi = (uint32_t*)sm1raw;                 // [2][64*20]
    uint32_t* sAlo = sAhi + 2 * 1280;
    uint4*    sBf  = (uint4*)(sm1raw + 4 * 4 * 1280);   // [2][512]

    const int tid = threadIdx.x;
    const int bx = blockIdx.x, by = blockIdx.y;
    const int lane = tid & 31, w = tid >> 5;
    const int g = lane >> 2, tg = lane & 3;
    const int mw = w & 1, nw = w >> 1;

    const int ar = tid >> 3, ac = (tid & 7) * 4;        // A loader
    const float* Abase = x + (size_t)ar * (T_ * I_) + (size_t)by * I_ + ac;

    float4 ra[4];
    uint4  rbf[4];
#pragma unroll
    for (int i = 0; i < 4; i++)
        ra[i] = __ldg((const float4*)(Abase + (size_t)(16 * i) * (T_ * I_)));
#pragma unroll
    for (int i = 0; i < 4; i++) {
        int idx = tid + i * 128;                        // 0..511
        int ln = idx & 31, nf = (idx >> 5) & 7, kbi = idx >> 8;
        rbf[i] = __ldg(&g_WxFrag[((size_t)(0 + kbi) * 256 + bx * 8 + nf) * 32 + ln]);
    }
#pragma unroll
    for (int i = 0; i < 4; i++) {
        uint16_t hx, lx, hy, ly, hz, lz, hw, lw;
        bsplit(ra[i].x, hx, lx); bsplit(ra[i].y, hy, ly);
        bsplit(ra[i].z, hz, lz); bsplit(ra[i].w, hw, lw);
        uint2 vh = {bpack(hx, hy), bpack(hz, hw)};
        uint2 vl = {bpack(lx, ly), bpack(lz, lw)};
        *(uint2*)&sAhi[(ar + 16 * i) * 20 + (ac >> 1)] = vh;
        *(uint2*)&sAlo[(ar + 16 * i) * 20 + (ac >> 1)] = vl;
        sBf[tid + i * 128] = rbf[i];
    }
    __syncthreads();

    float acc[2][4][4] = {};

    for (int kc = 0; kc < 16; kc++) {
        const int cb = kc & 1;
        const int abuf = cb * 1280;
        const int bbuf = cb * 512;
        if (kc < 15) {
#pragma unroll
            for (int i = 0; i < 4; i++)
                ra[i] = __ldg((const float4*)(Abase + (size_t)(16 * i) * (T_ * I_) + (kc + 1) * 32));
#pragma unroll
            for (int i = 0; i < 4; i++) {
                int idx = tid + i * 128;
                int ln = idx & 31, nf = (idx >> 5) & 7, kbi = idx >> 8;
                rbf[i] = __ldg(&g_WxFrag[((size_t)((kc + 1) * 2 + kbi) * 256 + bx * 8 + nf) * 32 + ln]);
            }
        }
#pragma unroll
        for (int kbi = 0; kbi < 2; kbi++) {
            uint32_t ahi[2][4], alo[2][4];
#pragma unroll
            for (int mf = 0; mf < 2; mf++) {
                int r0 = mw * 32 + mf * 16 + g;
                int wa = kbi * 8 + tg;
                ahi[mf][0] = sAhi[abuf + r0 * 20 + wa];
                ahi[mf][1] = sAhi[abuf + (r0 + 8) * 20 + wa];
                ahi[mf][2] = sAhi[abuf + r0 * 20 + wa + 4];
                ahi[mf][3] = sAhi[abuf + (r0 + 8) * 20 + wa + 4];
                alo[mf][0] = sAlo[abuf + r0 * 20 + wa];
                alo[mf][1] = sAlo[abuf + (r0 + 8) * 20 + wa];
                alo[mf][2] = sAlo[abuf + r0 * 20 + wa + 4];
                alo[mf][3] = sAlo[abuf + (r0 + 8) * 20 + wa + 4];
            }
#pragma unroll
            for (int nf = 0; nf < 4; nf++) {
                uint4 wf = sBf[bbuf + (kbi * 8 + nw * 4 + nf) * 32 + lane];
#pragma unroll
                for (int mf = 0; mf < 2; mf++) {
                    mma_bf16(acc[mf][nf], ahi[mf], wf.x, wf.y);
                    mma_bf16(acc[mf][nf], ahi[mf], wf.z, wf.w);
                    mma_bf16(acc[mf][nf], alo[mf], wf.x, wf.y);
                }
            }
        }
        if (kc < 15) {
            const int na = (cb ^ 1) * 1280;
            const int nb = (cb ^ 1) * 512;
            __syncthreads();
#pragma unroll
            for (int i = 0; i < 4; i++) {
                uint16_t hx, lx, hy, ly, hz, lz, hw, lw;
                bsplit(ra[i].x, hx, lx); bsplit(ra[i].y, hy, ly);
                bsplit(ra[i].z, hz, lz); bsplit(ra[i].w, hw, lw);
                uint2 vh = {bpack(hx, hy), bpack(hz, hw)};
                uint2 vl = {bpack(lx, ly), bpack(lz, lw)};
                *(uint2*)&sAhi[na + (ar + 16 * i) * 20 + (ac >> 1)] = vh;
                *(uint2*)&sAlo[na + (ar + 16 * i) * 20 + (ac >> 1)] = vl;
                sBf[nb + tid + i * 128] = rbf[i];
            }
            __syncthreads();
        }
    }

    const size_t outbase = (size_t)by * BG4;
#pragma unroll
    for (int mf = 0; mf < 2; mf++)
#pragma unroll
        for (int nf = 0; nf < 4; nf++) {
            int r = mw * 32 + mf * 16 + g;
            int cg = bx * 64 + nw * 32 + nf * 8 + tg * 2;
            float2 bb = *(const float2*)&g_bias[cg];
            float2 v0 = {acc[mf][nf][0] + bb.x, acc[mf][nf][1] + bb.y};
            float2 v1 = {acc[mf][nf][2] + bb.x, acc[mf][nf][3] + bb.y};
            *(float2*)&g_xproj[outbase + (size_t)r * G4 + cg] = v0;
            *(float2*)&g_xproj[outbase + (size_t)(r + 8) * G4 + cg] = v1;
        }
}

// ------------------------- K2: recurrence segment (3xBF16, direct-LDG) ------
// 128 CTAs x 128 thr, 1 CTA/SM (no SM sharing -> no doubled-SM stragglers).
// CTA (mb, jc): batch rows [32mb,+32), hidden [8jc,+8). Each warp: 2 m16
// tiles x its 8 k-blocks, A-frags direct from g_hP. Distributed epilogue:
// each thread owns 2 (b,j) elements.
#define SMEM2 (65536 + 16384)

__global__ void __launch_bounds__(128, 1) lstm_kernel(float* __restrict__ out, int t0) {
    extern __shared__ char smemraw[];
    uint4* sWf = (uint4*)smemraw;                 // [32 kb][4 nf][32 lane]
    float* sP  = (float*)(smemraw + 65536);       // [4 w][4 nf][32 b][8 j]

    const int tid = threadIdx.x;
    const int bxid = blockIdx.x;
    const int mb = bxid >> 6, jc = bxid & 63;
    const int lane = tid & 31, w = tid >> 5;
    const int g = lane >> 2, tg = lane & 3;
    const int bloc = tid >> 3, jloc = tid & 7;    // epilogue element 0: (bloc, jloc)
    const int jglob = jc * 8 + jloc;
    const int rowbase = mb * 32;

    // ---- load Wh fragments (layout contract from pack) ----
    {
        const uint4* src = g_WhFrag + (size_t)jc * 4096;
        for (int i = tid; i < 4096; i += 128) sWf[i] = src[i];
    }
    __syncthreads();

    // ---- per-thread state: 2 (b,j) elements (b = rowbase+bloc, +16) ----
    float cs[2];
    float xp[2][4];
#pragma unroll
    for (int e = 0; e < 2; e++) {
        int bglob = rowbase + bloc + 16 * e;
        cs[e] = g_cs[(size_t)bglob * H_ + jglob];
#pragma unroll
        for (int gate = 0; gate < 4; gate++)
            xp[e][gate] = __ldg(&g_xproj[(size_t)t0 * BG4 +
                                         (size_t)bglob * G4 + gate * 512 + jglob]);
    }

    for (int t = t0; t < t0 + SEG; t++) {
        // ---- GEMM: A fragments direct from global (64 LDG.64, one L2 RT) ----
        const uint2* hp = g_hP[t & 1];
        float acc1[2][4][4] = {}, acc2[2][4][4] = {}, acc3[2][4][4] = {};
#pragma unroll
        for (int kbi = 0; kbi < 8; kbi++) {
            const int kb = w * 8 + kbi;
            const int wa = kb * 8 + tg;
            const uint4* wfb = sWf + (kb * 4) * 32 + lane;
            uint4 wf[4];
#pragma unroll
            for (int nf = 0; nf < 4; nf++) wf[nf] = wfb[nf * 32];
#pragma unroll
            for (int mt = 0; mt < 2; mt++) {
                const int r0 = rowbase + mt * 16 + g;
                uint2 v0 = __ldcg(&hp[r0 * 256 + wa]);
                uint2 v1 = __ldcg(&hp[(r0 + 8) * 256 + wa]);
                uint2 v2 = __ldcg(&hp[r0 * 256 + wa + 4]);
                uint2 v3 = __ldcg(&hp[(r0 + 8) * 256 + wa + 4]);
                uint32_t ahi[4] = {v0.x, v1.x, v2.x, v3.x};
                uint32_t alo[4] = {v0.y, v1.y, v2.y, v3.y};
#pragma unroll
                for (int nf = 0; nf < 4; nf++) {
                    mma_bf16(acc1[mt][nf], ahi, wf[nf].x, wf[nf].y);
                    mma_bf16(acc2[mt][nf], ahi, wf[nf].z, wf[nf].w);
                    mma_bf16(acc3[mt][nf], alo, wf[nf].x, wf[nf].y);
                }
            }
        }

        // ---- publish partials: (mt; lane g,tg; q) -> element (b, j) ----
#pragma unroll
        for (int mt = 0; mt < 2; mt++)
#pragma unroll
            for (int nf = 0; nf < 4; nf++)
#pragma unroll
                for (int q = 0; q < 4; q++) {
                    int bq = mt * 16 + g + 8 * (q >> 1), jq = tg * 2 + (q & 1);
                    sP[((w * 4 + nf) * 32 + bq) * 8 + jq] =
                        acc1[mt][nf][q] + acc2[mt][nf][q] + acc3[mt][nf][q];
                }
        __syncthreads();

        // ---- distributed epilogue: each thread 2 elements ----
        float hout[2];
#pragma unroll
        for (int e = 0; e < 2; e++) {
            int b = bloc + 16 * e;
            float a4[4];
#pragma unroll
            for (int nf = 0; nf < 4; nf++) {
                float s = xp[e][nf];
#pragma unroll
                for (int ww = 0; ww < 4; ww++)
                    s += sP[((ww * 4 + nf) * 32 + b) * 8 + jloc];
                a4[nf] = s;
            }
            float fg = sigm(a4[0]);
            float ig = sigm(a4[1]);
            float og = sigm(a4[2]);
            float Cg = tanh_acc(a4[3]);
            cs[e] = fg * cs[e] + ig * Cg;
            hout[e] = og * tanh_acc(cs[e]);
        }

        if (t == T_ - 1) {
#pragma unroll
            for (int e = 0; e < 2; e++)
                out[(size_t)(rowbase + bloc + 16 * e) * H_ + jglob] = hout[e];
            break;
        }

        // ---- write h_{t+1}: pair via shfl, even lanes store 8B ----
#pragma unroll
        for (int e = 0; e < 2; e++) {
            int bglob = rowbase + bloc + 16 * e;
            uint16_t hh, hl;
            bsplit(hout[e], hh, hl);
            uint32_t mine = bpack(hh, hl);
            uint32_t other = __shfl_xor_sync(0xFFFFFFFF, mine, 1);
            if ((jloc & 1) == 0) {
                uint32_t hiw = (mine & 0xFFFFu) | (other << 16);
                uint32_t low = (mine >> 16) | (other & 0xFFFF0000u);
                __stcg((uint2*)&g_hP[(t + 1) & 1][bglob * 256 + jc * 4 + (jloc >> 1)],
                       make_uint2(hiw, low));
            }
        }
        __syncthreads();                          // h stores ordered before arrive
        if (tid == 0) red_rel(&g_count2[mb]);     // release arrival

        // xproj prefetch for t+1 in the barrier's shadow
#pragma unroll
        for (int e = 0; e < 2; e++) {
            int bglob = rowbase + bloc + 16 * e;
#pragma unroll
            for (int gate = 0; gate < 4; gate++)
                xp[e][gate] = __ldg(&g_xproj[(size_t)(t + 1) * BG4 +
                                             (size_t)bglob * G4 + gate * 512 + jglob]);
        }

        if (tid == 0) {
            while (ld_acq(&g_count2[mb]) < 64 * (t + 1)) {}
        }
        __syncthreads();
    }

    // ---- spill cell state for the next segment ----
#pragma unroll
    for (int e = 0; e < 2; e++)
        g_cs[(size_t)(rowbase + bloc + 16 * e) * H_ + jglob] = cs[e];
}

// ------------------------- launch ------------------------------------------
extern "C" void kernel_launch(void* const* d_in, const int* in_sizes, int n_in,
                              void* d_out, int out_size) {
    (void)in_sizes; (void)n_in; (void)out_size;
    const float* x  = (const float*)d_in[0];
    const float* Wf = (const float*)d_in[1];
    const float* bf = (const float*)d_in[2];
    const float* Wi = (const float*)d_in[3];
    const float* bi = (const float*)d_in[4];
    const float* Wo = (const float*)d_in[5];
    const float* bo = (const float*)d_in[6];
    const float* Wc = (const float*)d_in[7];
    const float* bc = (const float*)d_in[8];

    cudaFuncSetAttribute(xproj_kernel, cudaFuncAttributeMaxDynamicSharedMemorySize, K1_SMEM);
    cudaFuncSetAttribute(lstm_kernel, cudaFuncAttributeMaxDynamicSharedMemorySize, SMEM2);

    pack_kernel<<<4096, 256>>>(Wf, Wi, Wo, Wc, bf, bi, bo, bc);
    dim3 gx(32, 512);
    xproj_kernel<<<gx, 128, K1_SMEM>>>(x);
    for (int s = 0; s < 8; s++)
        lstm_kernel<<<NCG, 128, SMEM2>>>((float*)d_out, s * SEG);
}

// round 15
// speedup vs baseline: 1.0862x; 1.0862x over previous
#include <cuda_runtime.h>
#include <cuda_bf16.h>
#include <cstdint>

#define B_   64
#define T_   512
#define I_   512
#define H_   512
#define G4   2048
#define NCG  256
#define BG4  (B_ * G4)
#define SEG  64                                          // timesteps per K2 launch

// ------------------------- device scratch ----------------------------------
__device__ uint4    g_WxFrag[32 * 256 * 32];            // [kb][ncf][lane] bf16 frags (Wx)
__device__ uint4    g_WhFrag[64 * 4096];                // [jc][(kb*4+nf)*32+lane] (Wh)
__device__ float    g_bias[G4];
__device__ float    g_xproj[(size_t)T_ * BG4];          // [t][b][n] fp32
__device__ uint2    g_hP[2][B_ * 256];                  // [buf][b][k2] {hi-pair, lo-pair}
__device__ float    g_cs[B_ * H_];                      // cell state between segments
__device__ int      g_count4[4];                        // per-batch-group barrier counters

// ------------------------- helpers -----------------------------------------
__device__ __forceinline__ void bsplit(float v, uint16_t& hi, uint16_t& lo) {
    __nv_bfloat16 h = __float2bfloat16_rn(v);
    float r = v - __bfloat162float(h);
    __nv_bfloat16 l = __float2bfloat16_rn(r);
    hi = __bfloat16_as_ushort(h);
    lo = __bfloat16_as_ushort(l);
}
__device__ __forceinline__ uint32_t bpack(uint16_t e0, uint16_t e1) {
    return (uint32_t)e0 | ((uint32_t)e1 << 16);
}

__device__ __forceinline__ float sigm(float x) { return 1.0f / (1.0f + __expf(-x)); }
__device__ __forceinline__ float tanh_acc(float x) {
    return 1.0f - 2.0f / (__expf(2.0f * x) + 1.0f);
}

__device__ __forceinline__ int ld_acq(const int* p) {
    int v;
    asm volatile("ld.acquire.gpu.global.b32 %0, [%1];" : "=r"(v) : "l"(p) : "memory");
    return v;
}
__device__ __forceinline__ void red_rel(int* p) {
    asm volatile("red.release.gpu.global.add.s32 [%0], %1;" :: "l"(p), "r"(1) : "memory");
}

__device__ __forceinline__ void mma_bf16(float (&d)[4], const uint32_t (&a)[4],
                                         uint32_t b0, uint32_t b1) {
    asm volatile(
        "mma.sync.aligned.m16n8k16.row.col.f32.bf16.bf16.f32 "
        "{%0,%1,%2,%3}, {%4,%5,%6,%7}, {%8,%9}, {%0,%1,%2,%3};"
        : "+f"(d[0]), "+f"(d[1]), "+f"(d[2]), "+f"(d[3])
        : "r"(a[0]), "r"(a[1]), "r"(a[2]), "r"(a[3]), "r"(b0), "r"(b1));
}

__device__ __forceinline__ const float* wsel(int gate, const float* Wf, const float* Wi,
                                             const float* Wo, const float* Wc) {
    return gate == 0 ? Wf : gate == 1 ? Wi : gate == 2 ? Wo : Wc;
}

// ------------------------- K0: pack (frozen contracts) ----------------------
__global__ void pack_kernel(const float* __restrict__ Wf, const float* __restrict__ Wi,
                            const float* __restrict__ Wo, const float* __restrict__ Wc,
                            const float* __restrict__ bf, const float* __restrict__ bi,
                            const float* __restrict__ bo, const float* __restrict__ bc) {
    int idx = blockIdx.x * blockDim.x + threadIdx.x;
    if (idx < 32 * 256 * 32) {
        int lane = idx & 31, ncf = (idx >> 5) & 255, kb = idx >> 13;
        int g = lane >> 2, tg = lane & 3;
        int k0 = kb * 16 + 2 * tg;
        int col = ncf * 8 + g;
        int gate = col >> 9, j = col & 511;
        const float* W = wsel(gate, Wf, Wi, Wo, Wc);
        float v00 = W[(size_t)k0 * H_ + j];
        float v01 = W[(size_t)(k0 + 1) * H_ + j];
        float v10 = W[(size_t)(k0 + 8) * H_ + j];
        float v11 = W[(size_t)(k0 + 9) * H_ + j];
        uint16_t h00, l00, h01, l01, h10, l10, h11, l11;
        bsplit(v00, h00, l00); bsplit(v01, h01, l01);
        bsplit(v10, h10, l10); bsplit(v11, h11, l11);
        uint4 frag;
        frag.x = bpack(h00, h01);
        frag.y = bpack(h10, h11);
        frag.z = bpack(l00, l01);
        frag.w = bpack(l10, l11);
        g_WxFrag[idx] = frag;
    }
    if (idx < 64 * 4096) {
        int lane = idx & 31, nf = (idx >> 5) & 3, kb = (idx >> 7) & 31, jc = idx >> 12;
        int g = lane >> 2, tg = lane & 3;
        int k0 = kb * 16 + 2 * tg;
        const float* W = wsel(nf, Wf, Wi, Wo, Wc);
        const size_t base = (size_t)(I_ + k0) * H_ + jc * 8 + g;
        float v00 = W[base];
        float v01 = W[base + H_];
        float v10 = W[base + 8 * H_];
        float v11 = W[base + 9 * H_];
        uint16_t h00, l00, h01, l01, h10, l10, h11, l11;
        bsplit(v00, h00, l00); bsplit(v01, h01, l01);
        bsplit(v10, h10, l10); bsplit(v11, h11, l11);
        uint4 frag;
        frag.x = bpack(h00, h01);
        frag.y = bpack(h10, h11);
        frag.z = bpack(l00, l01);
        frag.w = bpack(l10, l11);
        g_WhFrag[(size_t)jc * 4096 + (kb * 4 + nf) * 32 + lane] = frag;
    }
    if (idx < G4) {
        int gate = idx >> 9, j = idx & 511;
        const float* b = gate == 0 ? bf : gate == 1 ? bi : gate == 2 ? bo : bc;
        g_bias[idx] = b[j];
    }
    if (idx < B_ * 256) g_hP[0][idx] = make_uint2(0u, 0u);   // h_0 = 0
    if (idx < B_ * H_) g_cs[idx] = 0.0f;
    if (idx < 4) g_count4[idx] = 0;
}

// ------------------------- K1: xproj = X @ Wx + bias (3xBF16) --------------
// BM=128 (2 timesteps x 64 batch), BN=128, BK=32. grid (16, 256). 256 thr,
// 8 warps = 4 m-slices x 2 n-slices, warp tile 32x64. Halves L2 traffic vs
// the old 64x64 tiling (B-frag reuse 2x, A reuse 2x).
#define K1_SMEM (2 * 128 * 20 * 4 * 2 + 2 * 1024 * 16)
__global__ void __launch_bounds__(256) xproj_kernel(const float* __restrict__ x) {
    extern __shared__ char sm1raw[];
    uint32_t* sAhi = (uint32_t*)sm1raw;                 // [2][128*20]
    uint32_t* sAlo = sAhi + 2 * 128 * 20;
    uint4*    sBf  = (uint4*)(sm1raw + 2 * 128 * 20 * 4 * 2);   // [2][1024]

    const int tid = threadIdx.x;
    const int bx = blockIdx.x, by = blockIdx.y;
    const int lane = tid & 31, w = tid >> 5;
    const int g = lane >> 2, tg = lane & 3;
    const int mw = w & 3, nw = w >> 2;

    // A loader: thread covers row r = tid>>1, cols [(tid&1)*16, +16)
    const int ar = tid >> 1, acb = (tid & 1) * 16;
    const int Rrow = by * 128 + ar;
    const int At = Rrow >> 6, Ab = Rrow & 63;
    const float* Abase = x + (size_t)Ab * (T_ * I_) + (size_t)At * I_ + acb;

    float4 ra[4];
    uint4  rbf[4];
#pragma unroll
    for (int i = 0; i < 4; i++)
        ra[i] = __ldg((const float4*)(Abase + 4 * i));
#pragma unroll
    for (int i = 0; i < 4; i++) {
        int idx = tid + i * 256;                        // 0..1023
        int ln = idx & 31, nf = (idx >> 5) & 15, kbi = idx >> 9;
        rbf[i] = __ldg(&g_WxFrag[((size_t)kbi * 256 + bx * 16 + nf) * 32 + ln]);
    }
#pragma unroll
    for (int i = 0; i < 4; i++) {
        uint16_t hx, lx, hy, ly, hz, lz, hw, lw;
        bsplit(ra[i].x, hx, lx); bsplit(ra[i].y, hy, ly);
        bsplit(ra[i].z, hz, lz); bsplit(ra[i].w, hw, lw);
        uint2 vh = {bpack(hx, hy), bpack(hz, hw)};
        uint2 vl = {bpack(lx, ly), bpack(lz, lw)};
        *(uint2*)&sAhi[ar * 20 + ((acb >> 1) + 2 * i)] = vh;
        *(uint2*)&sAlo[ar * 20 + ((acb >> 1) + 2 * i)] = vl;
        sBf[tid + i * 256] = rbf[i];
    }
    __syncthreads();

    float acc[2][8][4] = {};

    for (int kc = 0; kc < 16; kc++) {
        const int cb = kc & 1;
        const int abuf = cb * 128 * 20;
        const int bbuf = cb * 1024;
        if (kc < 15) {
#pragma unroll
            for (int i = 0; i < 4; i++)
                ra[i] = __ldg((const float4*)(Abase + (kc + 1) * 32 + 4 * i));
#pragma unroll
            for (int i = 0; i < 4; i++) {
                int idx = tid + i * 256;
                int ln = idx & 31, nf = (idx >> 5) & 15, kbi = idx >> 9;
                rbf[i] = __ldg(&g_WxFrag[((size_t)((kc + 1) * 2 + kbi) * 256 + bx * 16 + nf) * 32 + ln]);
            }
        }
#pragma unroll
        for (int kbi = 0; kbi < 2; kbi++) {
            uint32_t ahi[2][4], alo[2][4];
#pragma unroll
            for (int mf = 0; mf < 2; mf++) {
                int r0 = mw * 32 + mf * 16 + g;
                int wa = kbi * 8 + tg;
                ahi[mf][0] = sAhi[abuf + r0 * 20 + wa];
                ahi[mf][1] = sAhi[abuf + (r0 + 8) * 20 + wa];
                ahi[mf][2] = sAhi[abuf + r0 * 20 + wa + 4];
                ahi[mf][3] = sAhi[abuf + (r0 + 8) * 20 + wa + 4];
                alo[mf][0] = sAlo[abuf + r0 * 20 + wa];
                alo[mf][1] = sAlo[abuf + (r0 + 8) * 20 + wa];
                alo[mf][2] = sAlo[abuf + r0 * 20 + wa + 4];
                alo[mf][3] = sAlo[abuf + (r0 + 8) * 20 + wa + 4];
            }
#pragma unroll
            for (int nfi = 0; nfi < 8; nfi++) {
                uint4 wf = sBf[bbuf + (kbi * 16 + nw * 8 + nfi) * 32 + lane];
#pragma unroll
                for (int mf = 0; mf < 2; mf++) {
                    mma_bf16(acc[mf][nfi], ahi[mf], wf.x, wf.y);
                    mma_bf16(acc[mf][nfi], ahi[mf], wf.z, wf.w);
                    mma_bf16(acc[mf][nfi], alo[mf], wf.x, wf.y);
                }
            }
        }
        if (kc < 15) {
            const int na = (cb ^ 1) * 128 * 20;
            const int nb = (cb ^ 1) * 1024;
            __syncthreads();
#pragma unroll
            for (int i = 0; i < 4; i++) {
                uint16_t hx, lx, hy, ly, hz, lz, hw, lw;
                bsplit(ra[i].x, hx, lx); bsplit(ra[i].y, hy, ly);
                bsplit(ra[i].z, hz, lz); bsplit(ra[i].w, hw, lw);
                uint2 vh = {bpack(hx, hy), bpack(hz, hw)};
                uint2 vl = {bpack(lx, ly), bpack(lz, lw)};
                *(uint2*)&sAhi[na + ar * 20 + ((acb >> 1) + 2 * i)] = vh;
                *(uint2*)&sAlo[na + ar * 20 + ((acb >> 1) + 2 * i)] = vl;
                sBf[nb + tid + i * 256] = rbf[i];
            }
            __syncthreads();
        }
    }

    // epilogue: rows R = by*128 + mw*32 + mf*16 + g (+8); cols bx*128 + nw*64 + nfi*8 + tg*2
#pragma unroll
    for (int mf = 0; mf < 2; mf++)
#pragma unroll
        for (int nfi = 0; nfi < 8; nfi++) {
            size_t R = (size_t)by * 128 + mw * 32 + mf * 16 + g;
            int cg = bx * 128 + nw * 64 + nfi * 8 + tg * 2;
            float2 bb = *(const float2*)&g_bias[cg];
            float2 v0 = {acc[mf][nfi][0] + bb.x, acc[mf][nfi][1] + bb.y};
            float2 v1 = {acc[mf][nfi][2] + bb.x, acc[mf][nfi][3] + bb.y};
            *(float2*)&g_xproj[R * G4 + cg] = v0;
            *(float2*)&g_xproj[(R + 8) * G4 + cg] = v1;
        }
}

// ------------------------- K2: recurrence segment (round-13, reverted) ------
// 256 CTAs x 128 thr, 2 CTAs/SM. CTA (mb, jc): batch rows [16mb,+16),
// hidden [8jc,+8). A-frags direct from g_hP; distributed epilogue.
#define SMEM2 (65536 + 8192)

__global__ void __launch_bounds__(128, 2) lstm_kernel(float* __restrict__ out, int t0) {
    extern __shared__ char smemraw[];
    uint4* sWf = (uint4*)smemraw;                 // [32 kb][4 nf][32 lane]
    float* sP  = (float*)(smemraw + 65536);       // [4 w][4 nf][16 b][8 j]

    const int tid = threadIdx.x;
    const int bxid = blockIdx.x;
    const int mb = bxid >> 6, jc = bxid & 63;
    const int lane = tid & 31, w = tid >> 5;
    const int g = lane >> 2, tg = lane & 3;
    const int bloc = tid >> 3, jloc = tid & 7;    // epilogue element (b, j)
    const int bglob = mb * 16 + bloc;
    const int jglob = jc * 8 + jloc;
    const int rowbase = mb * 16;

    {
        const uint4* src = g_WhFrag + (size_t)jc * 4096;
        for (int i = tid; i < 4096; i += 128) sWf[i] = src[i];
    }
    __syncthreads();

    float cs = g_cs[(size_t)bglob * H_ + jglob];
    float xp[4];
#pragma unroll
    for (int gate = 0; gate < 4; gate++)
        xp[gate] = __ldg(&g_xproj[(size_t)t0 * BG4 + (size_t)bglob * G4 + gate * 512 + jglob]);

    for (int t = t0; t < t0 + SEG; t++) {
        const uint2* hp = g_hP[t & 1];
        float acc1[4][4] = {}, acc2[4][4] = {}, acc3[4][4] = {};
#pragma unroll
        for (int kbi = 0; kbi < 8; kbi++) {
            const int kb = w * 8 + kbi;
            const int wa = kb * 8 + tg;
            uint2 v0 = __ldcg(&hp[(rowbase + g) * 256 + wa]);
            uint2 v1 = __ldcg(&hp[(rowbase + g + 8) * 256 + wa]);
            uint2 v2 = __ldcg(&hp[(rowbase + g) * 256 + wa + 4]);
            uint2 v3 = __ldcg(&hp[(rowbase + g + 8) * 256 + wa + 4]);
            uint32_t ahi[4] = {v0.x, v1.x, v2.x, v3.x};
            uint32_t alo[4] = {v0.y, v1.y, v2.y, v3.y};
            const uint4* wfb = sWf + (kb * 4) * 32 + lane;
#pragma unroll
            for (int nf = 0; nf < 4; nf++) {
                uint4 wf = wfb[nf * 32];
                mma_bf16(acc1[nf], ahi, wf.x, wf.y);
                mma_bf16(acc2[nf], ahi, wf.z, wf.w);
                mma_bf16(acc3[nf], alo, wf.x, wf.y);
            }
        }

#pragma unroll
        for (int nf = 0; nf < 4; nf++)
#pragma unroll
            for (int q = 0; q < 4; q++) {
                int bq = g + 8 * (q >> 1), jq = tg * 2 + (q & 1);
                sP[((w * 4 + nf) * 16 + bq) * 8 + jq] =
                    acc1[nf][q] + acc2[nf][q] + acc3[nf][q];
            }
        __syncthreads();

        float a4[4];
#pragma unroll
        for (int nf = 0; nf < 4; nf++) {
            float s = xp[nf];
#pragma unroll
            for (int ww = 0; ww < 4; ww++)
                s += sP[((ww * 4 + nf) * 16 + bloc) * 8 + jloc];
            a4[nf] = s;
        }
        float fg = sigm(a4[0]);
        float ig = sigm(a4[1]);
        float og = sigm(a4[2]);
        float Cg = tanh_acc(a4[3]);
        cs = fg * cs + ig * Cg;
        float hout = og * tanh_acc(cs);

        if (t == T_ - 1) {
            out[(size_t)bglob * H_ + jglob] = hout;
            break;
        }

        uint16_t hh, hl;
        bsplit(hout, hh, hl);
        uint32_t mine = bpack(hh, hl);
        uint32_t other = __shfl_xor_sync(0xFFFFFFFF, mine, 1);
        if ((jloc & 1) == 0) {
            uint32_t hiw = (mine & 0xFFFFu) | (other << 16);
            uint32_t low = (mine >> 16) | (other & 0xFFFF0000u);
            __stcg((uint2*)&g_hP[(t + 1) & 1][bglob * 256 + jc * 4 + (jloc >> 1)],
                   make_uint2(hiw, low));
        }
        __syncthreads();
        if (tid == 0) red_rel(&g_count4[mb]);

#pragma unroll
        for (int gate = 0; gate < 4; gate++)
            xp[gate] = __ldg(&g_xproj[(size_t)(t + 1) * BG4 +
                                      (size_t)bglob * G4 + gate * 512 + jglob]);

        if (tid == 0) {
            while (ld_acq(&g_count4[mb]) < 64 * (t + 1)) {}
        }
        __syncthreads();
    }

    g_cs[(size_t)bglob * H_ + jglob] = cs;
}

// ------------------------- launch ------------------------------------------
extern "C" void kernel_launch(void* const* d_in, const int* in_sizes, int n_in,
                              void* d_out, int out_size) {
    (void)in_sizes; (void)n_in; (void)out_size;
    const float* x  = (const float*)d_in[0];
    const float* Wf = (const float*)d_in[1];
    const float* bf = (const float*)d_in[2];
    const float* Wi = (const float*)d_in[3];
    const float* bi = (const float*)d_in[4];
    const float* Wo = (const float*)d_in[5];
    const float* bo = (const float*)d_in[6];
    const float* Wc = (const float*)d_in[7];
    const float* bc = (const float*)d_in[8];

    cudaFuncSetAttribute(xproj_kernel, cudaFuncAttributeMaxDynamicSharedMemorySize, K1_SMEM);
    cudaFuncSetAttribute(lstm_kernel, cudaFuncAttributeMaxDynamicSharedMemorySize, SMEM2);

    pack_kernel<<<4096, 256>>>(Wf, Wi, Wo, Wc, bf, bi, bo, bc);
    dim3 gx(16, 256);
    xproj_kernel<<<gx, 256, K1_SMEM>>>(x);
    for (int s = 0; s < 8; s++)
        lstm_kernel<<<NCG, 128, SMEM2>>>((float*)d_out, s * SEG);
}

// round 16
// speedup vs baseline: 1.1245x; 1.0352x over previous
#include <cuda_runtime.h>
#include <cuda_bf16.h>
#include <cstdint>

#define B_   64
#define T_   512
#define I_   512
#define H_   512
#define G4   2048
#define NCG  256
#define BG4  (B_ * G4)
#define SEG  128                                         // timesteps per K2 launch

// ------------------------- device scratch ----------------------------------
__device__ uint4    g_WxFrag[32 * 256 * 32];            // [kb][ncf][lane] bf16 frags (Wx)
__device__ uint4    g_WhFrag[64 * 4096];                // [jc][(kb*4+nf)*32+lane] (Wh)
__device__ float    g_bias[G4];
__device__ float    g_xproj[(size_t)T_ * BG4];          // [t][b][n] fp32
__device__ uint2    g_hP[2][B_ * 256];                  // [buf][b][k2] {hi-pair, lo-pair}
__device__ float    g_cs[B_ * H_];                      // cell state between segments
__device__ int      g_count4[4];                        // per-batch-group barrier counters

// ------------------------- helpers -----------------------------------------
__device__ __forceinline__ void bsplit(float v, uint16_t& hi, uint16_t& lo) {
    __nv_bfloat16 h = __float2bfloat16_rn(v);
    float r = v - __bfloat162float(h);
    __nv_bfloat16 l = __float2bfloat16_rn(r);
    hi = __bfloat16_as_ushort(h);
    lo = __bfloat16_as_ushort(l);
}
__device__ __forceinline__ uint32_t bpack(uint16_t e0, uint16_t e1) {
    return (uint32_t)e0 | ((uint32_t)e1 << 16);
}

__device__ __forceinline__ float sigm(float x) { return 1.0f / (1.0f + __expf(-x)); }
__device__ __forceinline__ float tanh_acc(float x) {
    return 1.0f - 2.0f / (__expf(2.0f * x) + 1.0f);
}

__device__ __forceinline__ int ld_acq(const int* p) {
    int v;
    asm volatile("ld.acquire.gpu.global.b32 %0, [%1];" : "=r"(v) : "l"(p) : "memory");
    return v;
}
__device__ __forceinline__ void red_rel(int* p) {
    asm volatile("red.release.gpu.global.add.s32 [%0], %1;" :: "l"(p), "r"(1) : "memory");
}

__device__ __forceinline__ void mma_bf16(float (&d)[4], const uint32_t (&a)[4],
                                         uint32_t b0, uint32_t b1) {
    asm volatile(
        "mma.sync.aligned.m16n8k16.row.col.f32.bf16.bf16.f32 "
        "{%0,%1,%2,%3}, {%4,%5,%6,%7}, {%8,%9}, {%0,%1,%2,%3};"
        : "+f"(d[0]), "+f"(d[1]), "+f"(d[2]), "+f"(d[3])
        : "r"(a[0]), "r"(a[1]), "r"(a[2]), "r"(a[3]), "r"(b0), "r"(b1));
}

__device__ __forceinline__ const float* wsel(int gate, const float* Wf, const float* Wi,
                                             const float* Wo, const float* Wc) {
    return gate == 0 ? Wf : gate == 1 ? Wi : gate == 2 ? Wo : Wc;
}

// ------------------------- K0: pack (frozen contracts) ----------------------
__global__ void pack_kernel(const float* __restrict__ Wf, const float* __restrict__ Wi,
                            const float* __restrict__ Wo, const float* __restrict__ Wc,
                            const float* __restrict__ bf, const float* __restrict__ bi,
                            const float* __restrict__ bo, const float* __restrict__ bc) {
    int idx = blockIdx.x * blockDim.x + threadIdx.x;
    if (idx < 32 * 256 * 32) {
        int lane = idx & 31, ncf = (idx >> 5) & 255, kb = idx >> 13;
        int g = lane >> 2, tg = lane & 3;
        int k0 = kb * 16 + 2 * tg;
        int col = ncf * 8 + g;
        int gate = col >> 9, j = col & 511;
        const float* W = wsel(gate, Wf, Wi, Wo, Wc);
        float v00 = W[(size_t)k0 * H_ + j];
        float v01 = W[(size_t)(k0 + 1) * H_ + j];
        float v10 = W[(size_t)(k0 + 8) * H_ + j];
        float v11 = W[(size_t)(k0 + 9) * H_ + j];
        uint16_t h00, l00, h01, l01, h10, l10, h11, l11;
        bsplit(v00, h00, l00); bsplit(v01, h01, l01);
        bsplit(v10, h10, l10); bsplit(v11, h11, l11);
        uint4 frag;
        frag.x = bpack(h00, h01);
        frag.y = bpack(h10, h11);
        frag.z = bpack(l00, l01);
        frag.w = bpack(l10, l11);
        g_WxFrag[idx] = frag;
    }
    if (idx < 64 * 4096) {
        int lane = idx & 31, nf = (idx >> 5) & 3, kb = (idx >> 7) & 31, jc = idx >> 12;
        int g = lane >> 2, tg = lane & 3;
        int k0 = kb * 16 + 2 * tg;
        const float* W = wsel(nf, Wf, Wi, Wo, Wc);
        const size_t base = (size_t)(I_ + k0) * H_ + jc * 8 + g;
        float v00 = W[base];
        float v01 = W[base + H_];
        float v10 = W[base + 8 * H_];
        float v11 = W[base + 9 * H_];
        uint16_t h00, l00, h01, l01, h10, l10, h11, l11;
        bsplit(v00, h00, l00); bsplit(v01, h01, l01);
        bsplit(v10, h10, l10); bsplit(v11, h11, l11);
        uint4 frag;
        frag.x = bpack(h00, h01);
        frag.y = bpack(h10, h11);
        frag.z = bpack(l00, l01);
        frag.w = bpack(l10, l11);
        g_WhFrag[(size_t)jc * 4096 + (kb * 4 + nf) * 32 + lane] = frag;
    }
    if (idx < G4) {
        int gate = idx >> 9, j = idx & 511;
        const float* b = gate == 0 ? bf : gate == 1 ? bi : gate == 2 ? bo : bc;
        g_bias[idx] = b[j];
    }
    if (idx < B_ * 256) g_hP[0][idx] = make_uint2(0u, 0u);   // h_0 = 0
    if (idx < B_ * H_) g_cs[idx] = 0.0f;
    if (idx < 4) g_count4[idx] = 0;
}

// ------------------------- K1: xproj = X @ Wx + bias (3xBF16, round-13) ----
// BM=64 (batch), BN=64, BK=32. grid (32, 512). 128 thr, 4 warps.
#define K1_SMEM (4 * 4 * 1280 + 2 * 512 * 16)
__global__ void __launch_bounds__(128) xproj_kernel(const float* __restrict__ x) {
    extern __shared__ char sm1raw[];
    uint32_t* sAhi = (uint32_t*)sm1raw;                 // [2][64*20]
    uint32_t* sAlo = sAhi + 2 * 1280;
    uint4*    sBf  = (uint4*)(sm1raw + 4 * 4 * 1280);   // [2][512]

    const int tid = threadIdx.x;
    const int bx = blockIdx.x, by = blockIdx.y;
    const int lane = tid & 31, w = tid >> 5;
    const int g = lane >> 2, tg = lane & 3;
    const int mw = w & 1, nw = w >> 1;

    const int ar = tid >> 3, ac = (tid & 7) * 4;        // A loader
    const float* Abase = x + (size_t)ar * (T_ * I_) + (size_t)by * I_ + ac;

    float4 ra[4];
    uint4  rbf[4];
#pragma unroll
    for (int i = 0; i < 4; i++)
        ra[i] = __ldg((const float4*)(Abase + (size_t)(16 * i) * (T_ * I_)));
#pragma unroll
    for (int i = 0; i < 4; i++) {
        int idx = tid + i * 128;                        // 0..511
        int ln = idx & 31, nf = (idx >> 5) & 7, kbi = idx >> 8;
        rbf[i] = __ldg(&g_WxFrag[((size_t)(0 + kbi) * 256 + bx * 8 + nf) * 32 + ln]);
    }
#pragma unroll
    for (int i = 0; i < 4; i++) {
        uint16_t hx, lx, hy, ly, hz, lz, hw, lw;
        bsplit(ra[i].x, hx, lx); bsplit(ra[i].y, hy, ly);
        bsplit(ra[i].z, hz, lz); bsplit(ra[i].w, hw, lw);
        uint2 vh = {bpack(hx, hy), bpack(hz, hw)};
        uint2 vl = {bpack(lx, ly), bpack(lz, lw)};
        *(uint2*)&sAhi[(ar + 16 * i) * 20 + (ac >> 1)] = vh;
        *(uint2*)&sAlo[(ar + 16 * i) * 20 + (ac >> 1)] = vl;
        sBf[tid + i * 128] = rbf[i];
    }
    __syncthreads();

    float acc[2][4][4] = {};

    for (int kc = 0; kc < 16; kc++) {
        const int cb = kc & 1;
        const int abuf = cb * 1280;
        const int bbuf = cb * 512;
        if (kc < 15) {
#pragma unroll
            for (int i = 0; i < 4; i++)
                ra[i] = __ldg((const float4*)(Abase + (size_t)(16 * i) * (T_ * I_) + (kc + 1) * 32));
#pragma unroll
            for (int i = 0; i < 4; i++) {
                int idx = tid + i * 128;
                int ln = idx & 31, nf = (idx >> 5) & 7, kbi = idx >> 8;
                rbf[i] = __ldg(&g_WxFrag[((size_t)((kc + 1) * 2 + kbi) * 256 + bx * 8 + nf) * 32 + ln]);
            }
        }
#pragma unroll
        for (int kbi = 0; kbi < 2; kbi++) {
            uint32_t ahi[2][4], alo[2][4];
#pragma unroll
            for (int mf = 0; mf < 2; mf++) {
                int r0 = mw * 32 + mf * 16 + g;
                int wa = kbi * 8 + tg;
                ahi[mf][0] = sAhi[abuf + r0 * 20 + wa];
                ahi[mf][1] = sAhi[abuf + (r0 + 8) * 20 + wa];
                ahi[mf][2] = sAhi[abuf + r0 * 20 + wa + 4];
                ahi[mf][3] = sAhi[abuf + (r0 + 8) * 20 + wa + 4];
                alo[mf][0] = sAlo[abuf + r0 * 20 + wa];
                alo[mf][1] = sAlo[abuf + (r0 + 8) * 20 + wa];
                alo[mf][2] = sAlo[abuf + r0 * 20 + wa + 4];
                alo[mf][3] = sAlo[abuf + (r0 + 8) * 20 + wa + 4];
            }
#pragma unroll
            for (int nf = 0; nf < 4; nf++) {
                uint4 wf = sBf[bbuf + (kbi * 8 + nw * 4 + nf) * 32 + lane];
#pragma unroll
                for (int mf = 0; mf < 2; mf++) {
                    mma_bf16(acc[mf][nf], ahi[mf], wf.x, wf.y);
                    mma_bf16(acc[mf][nf], ahi[mf], wf.z, wf.w);
                    mma_bf16(acc[mf][nf], alo[mf], wf.x, wf.y);
                }
            }
        }
        if (kc < 15) {
            const int na = (cb ^ 1) * 1280;
            const int nb = (cb ^ 1) * 512;
            __syncthreads();
#pragma unroll
            for (int i = 0; i < 4; i++) {
                uint16_t hx, lx, hy, ly, hz, lz, hw, lw;
                bsplit(ra[i].x, hx, lx); bsplit(ra[i].y, hy, ly);
                bsplit(ra[i].z, hz, lz); bsplit(ra[i].w, hw, lw);
                uint2 vh = {bpack(hx, hy), bpack(hz, hw)};
                uint2 vl = {bpack(lx, ly), bpack(lz, lw)};
                *(uint2*)&sAhi[na + (ar + 16 * i) * 20 + (ac >> 1)] = vh;
                *(uint2*)&sAlo[na + (ar + 16 * i) * 20 + (ac >> 1)] = vl;
                sBf[nb + tid + i * 128] = rbf[i];
            }
            __syncthreads();
        }
    }

    const size_t outbase = (size_t)by * BG4;
#pragma unroll
    for (int mf = 0; mf < 2; mf++)
#pragma unroll
        for (int nf = 0; nf < 4; nf++) {
            int r = mw * 32 + mf * 16 + g;
            int cg = bx * 64 + nw * 32 + nf * 8 + tg * 2;
            float2 bb = *(const float2*)&g_bias[cg];
            float2 v0 = {acc[mf][nf][0] + bb.x, acc[mf][nf][1] + bb.y};
            float2 v1 = {acc[mf][nf][2] + bb.x, acc[mf][nf][3] + bb.y};
            *(float2*)&g_xproj[outbase + (size_t)r * G4 + cg] = v0;
            *(float2*)&g_xproj[outbase + (size_t)(r + 8) * G4 + cg] = v1;
        }
}

// ------------------------- K2: recurrence segment (round-13 shape) ----------
// 256 CTAs x 128 thr, 2 CTAs/SM. CTA (mb, jc): batch rows [16mb,+16),
// hidden [8jc,+8). A-frags direct from g_hP; distributed epilogue.
#define SMEM2 (65536 + 8192)

__global__ void __launch_bounds__(128, 2) lstm_kernel(float* __restrict__ out, int t0) {
    extern __shared__ char smemraw[];
    uint4* sWf = (uint4*)smemraw;                 // [32 kb][4 nf][32 lane]
    float* sP  = (float*)(smemraw + 65536);       // [4 w][4 nf][16 b][8 j]

    const int tid = threadIdx.x;
    const int bxid = blockIdx.x;
    const int mb = bxid >> 6, jc = bxid & 63;
    const int lane = tid & 31, w = tid >> 5;
    const int g = lane >> 2, tg = lane & 3;
    const int bloc = tid >> 3, jloc = tid & 7;    // epilogue element (b, j)
    const int bglob = mb * 16 + bloc;
    const int jglob = jc * 8 + jloc;
    const int rowbase = mb * 16;

    {
        const uint4* src = g_WhFrag + (size_t)jc * 4096;
        for (int i = tid; i < 4096; i += 128) sWf[i] = src[i];
    }
    __syncthreads();

    float cs = g_cs[(size_t)bglob * H_ + jglob];
    float xp[4];
#pragma unroll
    for (int gate = 0; gate < 4; gate++)
        xp[gate] = __ldg(&g_xproj[(size_t)t0 * BG4 + (size_t)bglob * G4 + gate * 512 + jglob]);

    for (int t = t0; t < t0 + SEG; t++) {
        const uint2* hp = g_hP[t & 1];
        float acc1[4][4] = {}, acc2[4][4] = {}, acc3[4][4] = {};
#pragma unroll
        for (int kbi = 0; kbi < 8; kbi++) {
            const int kb = w * 8 + kbi;
            const int wa = kb * 8 + tg;
            uint2 v0 = __ldcg(&hp[(rowbase + g) * 256 + wa]);
            uint2 v1 = __ldcg(&hp[(rowbase + g + 8) * 256 + wa]);
            uint2 v2 = __ldcg(&hp[(rowbase + g) * 256 + wa + 4]);
            uint2 v3 = __ldcg(&hp[(rowbase + g + 8) * 256 + wa + 4]);
            uint32_t ahi[4] = {v0.x, v1.x, v2.x, v3.x};
            uint32_t alo[4] = {v0.y, v1.y, v2.y, v3.y};
            const uint4* wfb = sWf + (kb * 4) * 32 + lane;
#pragma unroll
            for (int nf = 0; nf < 4; nf++) {
                uint4 wf = wfb[nf * 32];
                mma_bf16(acc1[nf], ahi, wf.x, wf.y);
                mma_bf16(acc2[nf], ahi, wf.z, wf.w);
                mma_bf16(acc3[nf], alo, wf.x, wf.y);
            }
        }

#pragma unroll
        for (int nf = 0; nf < 4; nf++)
#pragma unroll
            for (int q = 0; q < 4; q++) {
                int bq = g + 8 * (q >> 1), jq = tg * 2 + (q & 1);
                sP[((w * 4 + nf) * 16 + bq) * 8 + jq] =
                    acc1[nf][q] + acc2[nf][q] + acc3[nf][q];
            }
        __syncthreads();

        float a4[4];
#pragma unroll
        for (int nf = 0; nf < 4; nf++) {
            float s = xp[nf];
#pragma unroll
            for (int ww = 0; ww < 4; ww++)
                s += sP[((ww * 4 + nf) * 16 + bloc) * 8 + jloc];
            a4[nf] = s;
        }
        float fg = sigm(a4[0]);
        float ig = sigm(a4[1]);
        float og = sigm(a4[2]);
        float Cg = tanh_acc(a4[3]);
        cs = fg * cs + ig * Cg;
        float hout = og * tanh_acc(cs);

        if (t == T_ - 1) {
            out[(size_t)bglob * H_ + jglob] = hout;
            break;
        }

        uint16_t hh, hl;
        bsplit(hout, hh, hl);
        uint32_t mine = bpack(hh, hl);
        uint32_t other = __shfl_xor_sync(0xFFFFFFFF, mine, 1);
        if ((jloc & 1) == 0) {
            uint32_t hiw = (mine & 0xFFFFu) | (other << 16);
            uint32_t low = (mine >> 16) | (other & 0xFFFF0000u);
            __stcg((uint2*)&g_hP[(t + 1) & 1][bglob * 256 + jc * 4 + (jloc >> 1)],
                   make_uint2(hiw, low));
        }
        __syncthreads();
        if (tid == 0) red_rel(&g_count4[mb]);

#pragma unroll
        for (int gate = 0; gate < 4; gate++)
            xp[gate] = __ldg(&g_xproj[(size_t)(t + 1) * BG4 +
                                      (size_t)bglob * G4 + gate * 512 + jglob]);

        if (tid == 0) {
            while (ld_acq(&g_count4[mb]) < 64 * (t + 1)) {}
        }
        __syncthreads();
    }

    g_cs[(size_t)bglob * H_ + jglob] = cs;
}

// ------------------------- launch ------------------------------------------
extern "C" void kernel_launch(void* const* d_in, const int* in_sizes, int n_in,
                              void* d_out, int out_size) {
    (void)in_sizes; (void)n_in; (void)out_size;
    const float* x  = (const float*)d_in[0];
    const float* Wf = (const float*)d_in[1];
    const float* bf = (const float*)d_in[2];
    const float* Wi = (const float*)d_in[3];
    const float* bi = (const float*)d_in[4];
    const float* Wo = (const float*)d_in[5];
    const float* bo = (const float*)d_in[6];
    const float* Wc = (const float*)d_in[7];
    const float* bc = (const float*)d_in[8];

    cudaFuncSetAttribute(xproj_kernel, cudaFuncAttributeMaxDynamicSharedMemorySize, K1_SMEM);
    cudaFuncSetAttribute(lstm_kernel, cudaFuncAttributeMaxDynamicSharedMemorySize, SMEM2);

    pack_kernel<<<4096, 256>>>(Wf, Wi, Wo, Wc, bf, bi, bo, bc);
    dim3 gx(32, 512);
    xproj_kernel<<<gx, 128, K1_SMEM>>>(x);
    for (int s = 0; s < T_ / SEG; s++)
        lstm_kernel<<<NCG, 128, SMEM2>>>((float*)d_out, s * SEG);
}